// round 1
// baseline (speedup 1.0000x reference)
#include <cuda_runtime.h>
#include <cstdint>

// Problem dims (fixed by the reference)
#define BB  8
#define NN  128
#define FF  256
#define HH  256

// Scratch (allocation-free rule: __device__ globals)
__device__ float g_A[BB * HH];          //  8KB
__device__ float g_U[BB * NN * HH];     //  1MB
__device__ float g_V[BB * NN * HH];     //  1MB

// ---- packed f32x2 helpers (Blackwell) ----
__device__ __forceinline__ uint64_t pack2(float lo, float hi) {
    uint64_t r;
    asm("mov.b64 %0, {%1, %2};" : "=l"(r) : "f"(lo), "f"(hi));
    return r;
}
__device__ __forceinline__ void fma2(uint64_t& acc, uint64_t a, uint64_t b) {
    asm("fma.rn.f32x2 %0, %1, %2, %0;" : "+l"(acc) : "l"(a), "l"(b));
}
__device__ __forceinline__ void unpack2(uint64_t v, float& lo, float& hi) {
    asm("mov.b64 {%0, %1}, %2;" : "=f"(lo), "=f"(hi) : "l"(v));
}

// ============================================================================
// Kernel 1: fused
//   blocks [0,128):  GEMM  [1024 x 512] = relu(x)[1024 x 256] @ Wc[256 x 512]
//                    cols 0..255 -> U (W1 rows 256..511)
//                    cols 256..511 -> V (W1 rows 512..767)
//   blocks [128,136): per-batch A[b] = relu( relu(mean_i x[b,i]) @ Wp ) @ W1p + b1
// ============================================================================
__global__ void __launch_bounds__(256) k_prep(
    const float* __restrict__ x,    // [1024, 256]
    const float* __restrict__ Wp,   // [256, 256]
    const float* __restrict__ W1,   // [768, 256]
    const float* __restrict__ b1)   // [256]
{
    __shared__ __align__(16) union {
        struct {
            float              rst[32 * 66];   // relu(x) tile, k-major, padded
            unsigned long long wd [32 * 64];   // W tile, duplicated f32x2
        } g;
        struct {
            float s[256];
            float p[256];
        } a;
    } sm;

    const int blk = blockIdx.x;
    const int tid = threadIdx.x;

    if (blk < 128) {
        // ---------------- GEMM path ----------------
        const int rb = blk >> 3;            // row block 0..15 (64 rows each)
        const int cb = blk & 7;             // col block 0..7  (64 cols each)
        const int col  = tid & 63;          // 0..63
        const int r0   = (tid >> 6) * 16;   // local row base: 0,16,32,48

        const int wrow0 = (cb < 4) ? 256 : 512;
        const int h0    = (cb < 4) ? cb * 64 : (cb - 4) * 64;

        uint64_t acc[8];
        #pragma unroll
        for (int u = 0; u < 8; u++) acc[u] = 0ull;

        for (int k0 = 0; k0 < 256; k0 += 32) {
            __syncthreads();
            // relu(x) tile: 64 rows x 32 k, stored transposed (k-major)
            #pragma unroll
            for (int it = 0; it < 8; it++) {
                int idx = tid + it * 256;          // 0..2047
                int k = idx & 31, m = idx >> 5;    // coalesced read in k
                float v = x[(rb * 64 + m) * 256 + k0 + k];
                sm.g.rst[k * 66 + m] = fmaxf(v, 0.0f);
            }
            // weight tile, duplicated into both f32x2 halves
            #pragma unroll
            for (int it = 0; it < 8; it++) {
                int idx = tid + it * 256;
                int c = idx & 63, k = idx >> 6;    // coalesced read in c
                float w = W1[(wrow0 + k0 + k) * 256 + h0 + c];
                sm.g.wd[k * 64 + c] = pack2(w, w);
            }
            __syncthreads();

            #pragma unroll
            for (int k = 0; k < 32; k++) {
                uint64_t wv = sm.g.wd[k * 64 + col];
                const float* rr = &sm.g.rst[k * 66 + r0];   // 8B-aligned (66 even, r0 even)
                #pragma unroll
                for (int u = 0; u < 8; u++) {
                    uint64_t rp = *reinterpret_cast<const uint64_t*>(rr + 2 * u);
                    fma2(acc[u], rp, wv);
                }
            }
        }

        float* dst = (cb < 4) ? g_U : g_V;
        const int hcol = h0 + col;
        #pragma unroll
        for (int u = 0; u < 8; u++) {
            float lo, hi;
            unpack2(acc[u], lo, hi);
            int m = rb * 64 + r0 + 2 * u;
            dst[m * 256 + hcol]       = lo;
            dst[(m + 1) * 256 + hcol] = hi;
        }
    } else {
        // ---------------- A path (one CTA per batch) ----------------
        const int b = blk - 128;
        const int t = tid;  // 0..255

        // phase 1: mean over nodes
        float s0 = 0.f, s1 = 0.f, s2 = 0.f, s3 = 0.f;
        const float* xb = x + b * (NN * FF);
        #pragma unroll 4
        for (int i = 0; i < 128; i += 4) {
            s0 += xb[(i + 0) * 256 + t];
            s1 += xb[(i + 1) * 256 + t];
            s2 += xb[(i + 2) * 256 + t];
            s3 += xb[(i + 3) * 256 + t];
        }
        sm.a.s[t] = (s0 + s1 + s2 + s3) * (1.0f / 128.0f);
        __syncthreads();

        // phase 2: p = relu(s @ Wp)
        float p0 = 0.f, p1 = 0.f, p2 = 0.f, p3 = 0.f;
        #pragma unroll 4
        for (int f = 0; f < 256; f += 4) {
            p0 += sm.a.s[f + 0] * Wp[(f + 0) * 256 + t];
            p1 += sm.a.s[f + 1] * Wp[(f + 1) * 256 + t];
            p2 += sm.a.s[f + 2] * Wp[(f + 2) * 256 + t];
            p3 += sm.a.s[f + 3] * Wp[(f + 3) * 256 + t];
        }
        __syncthreads();
        sm.a.p[t] = fmaxf((p0 + p1) + (p2 + p3), 0.0f);
        __syncthreads();

        // phase 3: A = p @ W1[0:256] + b1
        float a0 = 0.f, a1 = 0.f, a2 = 0.f, a3 = 0.f;
        #pragma unroll 4
        for (int g = 0; g < 256; g += 4) {
            a0 += sm.a.p[g + 0] * W1[(g + 0) * 256 + t];
            a1 += sm.a.p[g + 1] * W1[(g + 1) * 256 + t];
            a2 += sm.a.p[g + 2] * W1[(g + 2) * 256 + t];
            a3 += sm.a.p[g + 3] * W1[(g + 3) * 256 + t];
        }
        g_A[b * 256 + t] = b1[t] + (a0 + a1) + (a2 + a3);
    }
}

// ============================================================================
// Kernel 2: pairwise readout
//   out[b,i,j] = sum_h relu(A[b,h] + U[b,i,h] + V[b,j,h]) * W2[h] + b2
//   CTA = (b, block of 8 i). V[b] fully staged in smem (pad 260 floats/row).
// ============================================================================
#define K3_SMEM (128 * 260 * 4 + 8 * 256 * 4 + 256 * 4)

__global__ void __launch_bounds__(256) k_pair(
    const float* __restrict__ W2,   // [256]
    const float* __restrict__ b2,   // [1]
    float* __restrict__ out)        // [8*128*128]
{
    extern __shared__ float smem[];
    float* Vs = smem;                    // [128][260]
    float* cs = smem + 128 * 260;        // [8][256]
    float* ws = cs + 8 * 256;            // [256]

    const int blk  = blockIdx.x;         // 0..127
    const int b    = blk >> 4;           // batch
    const int ib   = blk & 15;           // i block (8 i's)
    const int tid  = threadIdx.x;
    const int lane = tid & 31;
    const int w    = tid >> 5;

    // stage V[b] (128 x 256) into padded smem via float4
    const float4* Vg = reinterpret_cast<const float4*>(g_V + b * NN * HH);
    #pragma unroll
    for (int it = 0; it < 32; it++) {
        int idx = tid + it * 256;             // 0..8191
        int j = idx >> 6, q = idx & 63;
        reinterpret_cast<float4*>(Vs + j * 260)[q] = Vg[idx];
    }
    // stage c = A[b] + U[b, ib*8 + il]
    const float* Ug = g_U + (b * NN + ib * 8) * HH;
    const float* Ag = g_A + b * HH;
    #pragma unroll
    for (int it = 0; it < 8; it++) {
        int idx = tid + it * 256;             // 0..2047
        int il = idx >> 8, h = idx & 255;
        cs[il * 256 + h] = Ag[h] + Ug[il * 256 + h];
    }
    ws[tid] = W2[tid];
    __syncthreads();

    // warp mapping: 4 i-pairs x 2 j-halves
    const int ip = (w & 3) * 2;               // local i: ip, ip+1
    const int j0 = (w >> 2) * 64 + lane;      // j: j0, j0+32
    const float* c0 = cs + ip * 256;
    const float* c1 = c0 + 256;
    const float* v0 = Vs + j0 * 260;
    const float* v1 = v0 + 32 * 260;
    const float  bb = b2[0];

    float a00 = 0.f, a01 = 0.f, a10 = 0.f, a11 = 0.f;

    #pragma unroll 8
    for (int h = 0; h < 256; h += 4) {
        float4 vv0 = *reinterpret_cast<const float4*>(v0 + h);
        float4 vv1 = *reinterpret_cast<const float4*>(v1 + h);
        float4 cc0 = *reinterpret_cast<const float4*>(c0 + h);
        float4 cc1 = *reinterpret_cast<const float4*>(c1 + h);
        float4 wv  = *reinterpret_cast<const float4*>(ws + h);

        a00 += fmaxf(cc0.x + vv0.x, 0.f) * wv.x;
        a00 += fmaxf(cc0.y + vv0.y, 0.f) * wv.y;
        a00 += fmaxf(cc0.z + vv0.z, 0.f) * wv.z;
        a00 += fmaxf(cc0.w + vv0.w, 0.f) * wv.w;

        a01 += fmaxf(cc0.x + vv1.x, 0.f) * wv.x;
        a01 += fmaxf(cc0.y + vv1.y, 0.f) * wv.y;
        a01 += fmaxf(cc0.z + vv1.z, 0.f) * wv.z;
        a01 += fmaxf(cc0.w + vv1.w, 0.f) * wv.w;

        a10 += fmaxf(cc1.x + vv0.x, 0.f) * wv.x;
        a10 += fmaxf(cc1.y + vv0.y, 0.f) * wv.y;
        a10 += fmaxf(cc1.z + vv0.z, 0.f) * wv.z;
        a10 += fmaxf(cc1.w + vv0.w, 0.f) * wv.w;

        a11 += fmaxf(cc1.x + vv1.x, 0.f) * wv.x;
        a11 += fmaxf(cc1.y + vv1.y, 0.f) * wv.y;
        a11 += fmaxf(cc1.z + vv1.z, 0.f) * wv.z;
        a11 += fmaxf(cc1.w + vv1.w, 0.f) * wv.w;
    }

    const int i0 = ib * 8 + ip;
    float* ob = out + b * (NN * NN);
    ob[(i0    ) * NN + j0     ] = a00 + bb;
    ob[(i0    ) * NN + j0 + 32] = a01 + bb;
    ob[(i0 + 1) * NN + j0     ] = a10 + bb;
    ob[(i0 + 1) * NN + j0 + 32] = a11 + bb;
}

// ============================================================================
extern "C" void kernel_launch(void* const* d_in, const int* in_sizes, int n_in,
                              void* d_out, int out_size) {
    const float* x  = (const float*)d_in[0];
    // d_in[1] = mask (all ones; reference ignores it for pooling) — unused
    const float* Wp = (const float*)d_in[2];
    const float* W1 = (const float*)d_in[3];
    const float* b1 = (const float*)d_in[4];
    const float* W2 = (const float*)d_in[5];
    const float* b2 = (const float*)d_in[6];
    float* out = (float*)d_out;

    cudaFuncSetAttribute(k_pair, cudaFuncAttributeMaxDynamicSharedMemorySize, K3_SMEM);

    k_prep<<<136, 256>>>(x, Wp, W1, b1);
    k_pair<<<128, 256, K3_SMEM>>>(W2, b2, out);
}